// round 1
// baseline (speedup 1.0000x reference)
#include <cuda_runtime.h>
#include <cuda_bf16.h>

// Problem constants (fixed by the dataset)
#define NNODES 50000
#define NDIM   64
#define NEDGES 800000
#define MAXD   64          // SMEM fast-path degree cap (P(exceed) ~ 1e-5 over all nodes)
#define SCAN_BS 512

// -------- device scratch (no allocation allowed) --------
__device__ int   g_deg[NNODES];
__device__ int   g_cursor[NNODES];
__device__ int   g_starts[NNODES + 1];
__device__ int   g_bsums[(NNODES + SCAN_BS - 1) / SCAN_BS + 1];
__device__ int   g_srow[NEDGES];
__device__ float g_sw[NEDGES];

// -------- kernel 1: zero counters --------
__global__ void k_zero() {
    int i = blockIdx.x * blockDim.x + threadIdx.x;
    if (i < NNODES) {
        g_deg[i] = 0;
        g_cursor[i] = 0;
    }
}

// -------- kernel 2: count in-degree --------
__global__ void k_count(const int* __restrict__ edge_index) {
    int e = blockIdx.x * blockDim.x + threadIdx.x;
    if (e < NEDGES) {
        int dst = edge_index[NEDGES + e];   // edge_index[1, e]
        atomicAdd(&g_deg[dst], 1);
    }
}

// -------- kernel 3: per-block exclusive scan --------
__global__ void k_scan1() {
    __shared__ int sh[SCAN_BS];
    int tid = threadIdx.x;
    int gid = blockIdx.x * SCAN_BS + tid;
    int v = (gid < NNODES) ? g_deg[gid] : 0;
    sh[tid] = v;
    __syncthreads();
    // Hillis-Steele inclusive scan
    for (int off = 1; off < SCAN_BS; off <<= 1) {
        int t = (tid >= off) ? sh[tid - off] : 0;
        __syncthreads();
        sh[tid] += t;
        __syncthreads();
    }
    if (gid < NNODES) g_starts[gid] = sh[tid] - v;   // exclusive
    if (tid == SCAN_BS - 1) g_bsums[blockIdx.x] = sh[tid];
}

// -------- kernel 4: scan of block sums (single thread; ~100 elems) --------
__global__ void k_scan2(int nblocks) {
    if (threadIdx.x == 0 && blockIdx.x == 0) {
        int acc = 0;
        for (int i = 0; i < nblocks; i++) {
            int t = g_bsums[i];
            g_bsums[i] = acc;
            acc += t;
        }
    }
}

// -------- kernel 5: add block offsets --------
__global__ void k_scan3() {
    int gid = blockIdx.x * SCAN_BS + threadIdx.x;
    if (gid < NNODES) g_starts[gid] += g_bsums[blockIdx.x];
    if (gid == 0) g_starts[NNODES] = NEDGES;
}

// -------- kernel 6: scatter (counting sort by destination) --------
__global__ void k_scatter(const int* __restrict__ edge_index,
                          const float* __restrict__ edge_weight) {
    int e = blockIdx.x * blockDim.x + threadIdx.x;
    if (e >= NEDGES) return;
    int dst = edge_index[NEDGES + e];
    int p = atomicAdd(&g_cursor[dst], 1);
    int idx = g_starts[dst] + p;
    g_srow[idx] = edge_index[e];    // edge_index[0, e] (source)
    g_sw[idx]   = edge_weight[e];
}

// -------- kernel 7: per-node per-channel lower median --------
// One block per node, one thread per channel (NDIM=64).
__global__ void __launch_bounds__(NDIM) k_median(const float* __restrict__ x,
                                                 float* __restrict__ out) {
    int n = blockIdx.x;
    int d = threadIdx.x;

    int s   = g_starts[n];
    int deg = g_starts[n + 1] - s;

    if (deg == 0) {
        out[n * NDIM + d] = 0.0f;
        return;
    }

    int k = (deg - 1) >> 1;

    if (deg <= MAXD) {
        __shared__ float vals[MAXD * NDIM];
        __shared__ int   rows[MAXD];
        __shared__ float ws[MAXD];

        for (int i = d; i < deg; i += NDIM) {
            rows[i] = g_srow[s + i];
            ws[i]   = g_sw[s + i];
        }
        __syncthreads();

        // Gather weighted messages. Thread d writes/reads only column d:
        // addresses consecutive across the warp -> conflict-free, no sync needed.
        for (int j = 0; j < deg; j++) {
            vals[j * NDIM + d] = x[rows[j] * NDIM + d] * ws[j];
        }

        // Rank-count selection of the k-th smallest (lower median).
        const float* col = &vals[d];
        float med = 0.0f;
        for (int i = 0; i < deg; i++) {
            float vi = col[i * NDIM];
            int less = 0, eq = 0;
            for (int j = 0; j < deg; j++) {
                float vj = col[j * NDIM];
                less += (vj < vi);
                eq   += (vj == vi);
            }
            if (less <= k && k < less + eq) { med = vi; break; }
        }
        out[n * NDIM + d] = med;
    } else {
        // Slow path for pathological degrees (>MAXD): stream from global.
        // Essentially never taken for this dataset; correctness guarantee only.
        float med = 0.0f;
        for (int i = 0; i < deg; i++) {
            float vi = x[g_srow[s + i] * NDIM + d] * g_sw[s + i];
            int less = 0, eq = 0;
            for (int j = 0; j < deg; j++) {
                float vj = x[g_srow[s + j] * NDIM + d] * g_sw[s + j];
                less += (vj < vi);
                eq   += (vj == vi);
            }
            if (less <= k && k < less + eq) { med = vi; break; }
        }
        out[n * NDIM + d] = med;
    }
}

extern "C" void kernel_launch(void* const* d_in, const int* in_sizes, int n_in,
                              void* d_out, int out_size) {
    const float* x           = (const float*)d_in[0];
    const int*   edge_index  = (const int*)d_in[1];
    const float* edge_weight = (const float*)d_in[2];
    float*       out         = (float*)d_out;

    (void)in_sizes; (void)n_in; (void)out_size;

    const int nb_scan = (NNODES + SCAN_BS - 1) / SCAN_BS;

    k_zero   <<<(NNODES + 255) / 256, 256>>>();
    k_count  <<<(NEDGES + 255) / 256, 256>>>(edge_index);
    k_scan1  <<<nb_scan, SCAN_BS>>>();
    k_scan2  <<<1, 32>>>(nb_scan);
    k_scan3  <<<nb_scan, SCAN_BS>>>();
    k_scatter<<<(NEDGES + 255) / 256, 256>>>(edge_index, edge_weight);
    k_median <<<NNODES, NDIM>>>(x, out);
}

// round 3
// speedup vs baseline: 2.4214x; 2.4214x over previous
#include <cuda_runtime.h>
#include <cuda_bf16.h>
#include <math_constants.h>

// Problem constants (fixed by the dataset)
#define NNODES 50000
#define NDIM   64
#define NEDGES 800000
#define SCAN_BS 512

// -------- device scratch (no allocation allowed) --------
__device__ int   g_deg[NNODES];
__device__ int   g_cursor[NNODES];
__device__ int   g_starts[NNODES + 1];
__device__ int   g_bsums[(NNODES + SCAN_BS - 1) / SCAN_BS + 1];
__device__ int   g_srow[NEDGES];
__device__ float g_sw[NEDGES];

// -------- kernel 1: zero counters --------
__global__ void k_zero() {
    int i = blockIdx.x * blockDim.x + threadIdx.x;
    if (i < NNODES) {
        g_deg[i] = 0;
        g_cursor[i] = 0;
    }
}

// -------- kernel 2: count in-degree --------
__global__ void k_count(const int* __restrict__ edge_index) {
    int e = blockIdx.x * blockDim.x + threadIdx.x;
    if (e < NEDGES) {
        int dst = edge_index[NEDGES + e];   // edge_index[1, e]
        atomicAdd(&g_deg[dst], 1);
    }
}

// -------- kernel 3: per-block exclusive scan --------
__global__ void k_scan1() {
    __shared__ int sh[SCAN_BS];
    int tid = threadIdx.x;
    int gid = blockIdx.x * SCAN_BS + tid;
    int v = (gid < NNODES) ? g_deg[gid] : 0;
    sh[tid] = v;
    __syncthreads();
    for (int off = 1; off < SCAN_BS; off <<= 1) {
        int t = (tid >= off) ? sh[tid - off] : 0;
        __syncthreads();
        sh[tid] += t;
        __syncthreads();
    }
    if (gid < NNODES) g_starts[gid] = sh[tid] - v;   // exclusive
    if (tid == SCAN_BS - 1) g_bsums[blockIdx.x] = sh[tid];
}

// -------- kernel 4: parallel exclusive scan of block sums (<=128 blocks) --------
__global__ void k_scan2(int nblocks) {
    __shared__ int sh[128];
    int tid = threadIdx.x;
    int v = (tid < nblocks) ? g_bsums[tid] : 0;
    sh[tid] = v;
    __syncthreads();
    for (int off = 1; off < 128; off <<= 1) {
        int t = (tid >= off) ? sh[tid - off] : 0;
        __syncthreads();
        sh[tid] += t;
        __syncthreads();
    }
    if (tid < nblocks) g_bsums[tid] = sh[tid] - v;   // exclusive
}

// -------- kernel 5: add block offsets --------
__global__ void k_scan3() {
    int gid = blockIdx.x * SCAN_BS + threadIdx.x;
    if (gid < NNODES) g_starts[gid] += g_bsums[blockIdx.x];
    if (gid == 0) g_starts[NNODES] = NEDGES;
}

// -------- kernel 6: scatter (counting sort by destination) --------
__global__ void k_scatter(const int* __restrict__ edge_index,
                          const float* __restrict__ edge_weight) {
    int e = blockIdx.x * blockDim.x + threadIdx.x;
    if (e >= NEDGES) return;
    int dst = edge_index[NEDGES + e];
    int p = atomicAdd(&g_cursor[dst], 1);
    int idx = g_starts[dst] + p;
    g_srow[idx] = edge_index[e];    // edge_index[0, e] (source)
    g_sw[idx]   = edge_weight[e];
}

// -------- register-resident gather + bitonic sort + k-select --------
// P = padded size (power of two), deg <= P. Returns the k-th smallest of the
// deg weighted messages for channel d. Pads with +inf (never selected: k < deg).
template<int P>
__device__ __forceinline__ float median_reg(const int* __restrict__ rows,
                                            const float* __restrict__ ws,
                                            const float* __restrict__ x,
                                            int d, int deg, int k) {
    float v[P];
#pragma unroll
    for (int j = 0; j < P; j++) {
        v[j] = (j < deg) ? x[rows[j] * NDIM + d] * ws[j] : CUDART_INF_F;
    }
    // fully-unrolled bitonic sort, ascending
#pragma unroll
    for (int size = 2; size <= P; size <<= 1) {
#pragma unroll
        for (int stride = size >> 1; stride > 0; stride >>= 1) {
#pragma unroll
            for (int i = 0; i < P; i++) {
                int j = i ^ stride;
                if (j > i) {
                    bool up = ((i & size) == 0);
                    float a = v[i], b = v[j];
                    float lo = fminf(a, b), hi = fmaxf(a, b);
                    v[i] = up ? lo : hi;
                    v[j] = up ? hi : lo;
                }
            }
        }
    }
    // select element k (SEL tree)
    float r = v[0];
#pragma unroll
    for (int i = 1; i < P; i++) r = (k == i) ? v[i] : r;
    return r;
}

// -------- kernel 7: per-node per-channel lower median --------
// One block per node, one thread per channel. All threads in a block share deg,
// so the degree-bucket dispatch is uniform (no divergence).
__global__ void __launch_bounds__(NDIM) k_median(const float* __restrict__ x,
                                                 float* __restrict__ out) {
    int n = blockIdx.x;
    int d = threadIdx.x;

    int s   = g_starts[n];
    int deg = g_starts[n + 1] - s;

    if (deg == 0) {
        out[n * NDIM + d] = 0.0f;
        return;
    }

    int k = (deg - 1) >> 1;

    if (deg <= 32) {
        __shared__ int   rows[32];
        __shared__ float ws[32];
        if (d < deg) {
            rows[d] = g_srow[s + d];
            ws[d]   = g_sw[s + d];
        }
        __syncthreads();

        float med;
        if      (deg <= 8)  med = median_reg<8> (rows, ws, x, d, deg, k);
        else if (deg <= 16) med = median_reg<16>(rows, ws, x, d, deg, k);
        else                med = median_reg<32>(rows, ws, x, d, deg, k);
        out[n * NDIM + d] = med;
    } else {
        // Rare path (P(deg>32) ~ 1e-4 per node): global rank-count selection.
        float med = 0.0f;
        for (int i = 0; i < deg; i++) {
            float vi = x[g_srow[s + i] * NDIM + d] * g_sw[s + i];
            int less = 0, eq = 0;
            for (int j = 0; j < deg; j++) {
                float vj = x[g_srow[s + j] * NDIM + d] * g_sw[s + j];
                less += (vj < vi);
                eq   += (vj == vi);
            }
            if (less <= k && k < less + eq) { med = vi; break; }
        }
        out[n * NDIM + d] = med;
    }
}

extern "C" void kernel_launch(void* const* d_in, const int* in_sizes, int n_in,
                              void* d_out, int out_size) {
    const float* x           = (const float*)d_in[0];
    const int*   edge_index  = (const int*)d_in[1];
    const float* edge_weight = (const float*)d_in[2];
    float*       out         = (float*)d_out;

    (void)in_sizes; (void)n_in; (void)out_size;

    const int nb_scan = (NNODES + SCAN_BS - 1) / SCAN_BS;

    k_zero   <<<(NNODES + 255) / 256, 256>>>();
    k_count  <<<(NEDGES + 255) / 256, 256>>>(edge_index);
    k_scan1  <<<nb_scan, SCAN_BS>>>();
    k_scan2  <<<1, 128>>>(nb_scan);
    k_scan3  <<<nb_scan, SCAN_BS>>>();
    k_scatter<<<(NEDGES + 255) / 256, 256>>>(edge_index, edge_weight);
    k_median <<<NNODES, NDIM>>>(x, out);
}

// round 4
// speedup vs baseline: 2.4597x; 1.0158x over previous
#include <cuda_runtime.h>
#include <cuda_bf16.h>
#include <math_constants.h>

// Problem constants (fixed by the dataset)
#define NNODES 50000
#define NDIM   64
#define NEDGES 800000

// -------- device scratch (no allocation allowed) --------
__device__ int   g_deg[NNODES];
__device__ int   g_cursor[NNODES];
__device__ int   g_starts[NNODES];
__device__ int   g_total;
__device__ int   g_srow[NEDGES];
__device__ float g_sw[NEDGES];

// -------- kernel 1: zero counters --------
__global__ void k_zero() {
    int i = blockIdx.x * blockDim.x + threadIdx.x;
    if (i < NNODES) {
        g_deg[i] = 0;
        g_cursor[i] = 0;
    }
    if (i == 0) g_total = 0;
}

// -------- kernel 2: count in-degree --------
__global__ void k_count(const int* __restrict__ edge_index) {
    int e = blockIdx.x * blockDim.x + threadIdx.x;
    if (e < NEDGES) {
        int dst = edge_index[NEDGES + e];   // edge_index[1, e]
        atomicAdd(&g_deg[dst], 1);
    }
}

// -------- kernel 3: segment offsets in ONE kernel --------
// Per-block inclusive scan of degrees + one atomicAdd of the block total on a
// global counter. Segment ordering across blocks is nondeterministic, but
// segments are disjoint and the median is order-invariant, so the OUTPUT is
// deterministic.
#define OFF_BS 256
__global__ void k_offsets() {
    __shared__ int sh[OFF_BS];
    __shared__ int base;
    int tid = threadIdx.x;
    int gid = blockIdx.x * OFF_BS + tid;
    int v = (gid < NNODES) ? g_deg[gid] : 0;
    sh[tid] = v;
    __syncthreads();
    for (int off = 1; off < OFF_BS; off <<= 1) {
        int t = (tid >= off) ? sh[tid - off] : 0;
        __syncthreads();
        sh[tid] += t;
        __syncthreads();
    }
    if (tid == OFF_BS - 1) base = atomicAdd(&g_total, sh[tid]);
    __syncthreads();
    if (gid < NNODES) g_starts[gid] = base + sh[tid] - v;   // exclusive within block
}

// -------- kernel 4: scatter (counting sort by destination) --------
__global__ void k_scatter(const int* __restrict__ edge_index,
                          const float* __restrict__ edge_weight) {
    int e = blockIdx.x * blockDim.x + threadIdx.x;
    if (e >= NEDGES) return;
    int dst = edge_index[NEDGES + e];
    int p = atomicAdd(&g_cursor[dst], 1);
    int idx = g_starts[dst] + p;
    g_srow[idx] = edge_index[e];    // edge_index[0, e] (source)
    g_sw[idx]   = edge_weight[e];
}

// -------- Batcher odd-even merge sort (compile-time network) --------
__device__ __forceinline__ void cas_f(float& a, float& b) {
    float lo = fminf(a, b);
    float hi = fmaxf(a, b);
    a = lo; b = hi;
}

template<int LO, int N, int R>
struct OEMerge {
    static __device__ __forceinline__ void run(float* v) {
        constexpr int M = R * 2;
        if constexpr (M < N) {
            OEMerge<LO, N, M>::run(v);
            OEMerge<LO + R, N, M>::run(v);
#pragma unroll
            for (int i = LO + R; i + R < LO + N; i += M)
                cas_f(v[i], v[i + R]);
        } else {
            cas_f(v[LO], v[LO + R]);
        }
    }
};

template<int LO, int N>
struct OESort {
    static __device__ __forceinline__ void run(float* v) {
        if constexpr (N > 1) {
            constexpr int M = N / 2;
            OESort<LO, M>::run(v);
            OESort<LO + M, M>::run(v);
            OEMerge<LO, N, 1>::run(v);
        }
    }
};

// -------- register-resident gather + Batcher sort + k-select --------
// P = padded size (power of two), deg <= P. Pads with +inf (never selected).
template<int P>
__device__ __forceinline__ float median_reg(const int* __restrict__ rows,
                                            const float* __restrict__ ws,
                                            const float* __restrict__ x,
                                            int d, int deg, int k) {
    float v[P];
#pragma unroll
    for (int j = 0; j < P; j++) {
        v[j] = (j < deg) ? x[rows[j] * NDIM + d] * ws[j] : CUDART_INF_F;
    }
    OESort<0, P>::run(v);
    float r = v[0];
#pragma unroll
    for (int i = 1; i < P; i++) r = (k == i) ? v[i] : r;
    return r;
}

// -------- kernel 5: per-node per-channel lower median --------
// 4 nodes per block (64 threads each). Node boundaries align with warp
// boundaries, so the degree-bucket branch is warp-uniform.
#define NODES_PER_BLK 4
__global__ void __launch_bounds__(NDIM * NODES_PER_BLK)
k_median(const float* __restrict__ x, float* __restrict__ out) {
    int n = blockIdx.x * NODES_PER_BLK + threadIdx.y;
    int d = threadIdx.x;
    if (n >= NNODES) return;

    int deg = g_deg[n];
    if (deg == 0) {
        out[n * NDIM + d] = 0.0f;
        return;
    }
    int s = g_starts[n];
    int k = (deg - 1) >> 1;

    if (deg <= 32) {
        __shared__ int   rows[NODES_PER_BLK][32];
        __shared__ float ws[NODES_PER_BLK][32];
        if (d < deg) {
            rows[threadIdx.y][d] = g_srow[s + d];
            ws[threadIdx.y][d]   = g_sw[s + d];
        }
        __syncwarp();   // 2 warps per node; each warp only reads what it wrote?
        // NOTE: both warps of a node read all deg entries, but entries are
        // written by warp 0 (d<32 always covers deg<=32). Need cross-warp
        // visibility -> use a block-level fence instead:
        __syncthreads();

        float med;
        if      (deg <= 8)  med = median_reg<8> (rows[threadIdx.y], ws[threadIdx.y], x, d, deg, k);
        else if (deg <= 16) med = median_reg<16>(rows[threadIdx.y], ws[threadIdx.y], x, d, deg, k);
        else                med = median_reg<32>(rows[threadIdx.y], ws[threadIdx.y], x, d, deg, k);
        out[n * NDIM + d] = med;
    } else {
        __syncthreads();   // keep barrier participation uniform across the block
        // Rare path (P(deg>32) ~ 1e-4 per node): global rank-count selection.
        float med = 0.0f;
        for (int i = 0; i < deg; i++) {
            float vi = x[g_srow[s + i] * NDIM + d] * g_sw[s + i];
            int less = 0, eq = 0;
            for (int j = 0; j < deg; j++) {
                float vj = x[g_srow[s + j] * NDIM + d] * g_sw[s + j];
                less += (vj < vi);
                eq   += (vj == vi);
            }
            if (less <= k && k < less + eq) { med = vi; break; }
        }
        out[n * NDIM + d] = med;
    }
}

extern "C" void kernel_launch(void* const* d_in, const int* in_sizes, int n_in,
                              void* d_out, int out_size) {
    const float* x           = (const float*)d_in[0];
    const int*   edge_index  = (const int*)d_in[1];
    const float* edge_weight = (const float*)d_in[2];
    float*       out         = (float*)d_out;

    (void)in_sizes; (void)n_in; (void)out_size;

    k_zero   <<<(NNODES + 255) / 256, 256>>>();
    k_count  <<<(NEDGES + 255) / 256, 256>>>(edge_index);
    k_offsets<<<(NNODES + OFF_BS - 1) / OFF_BS, OFF_BS>>>();
    k_scatter<<<(NEDGES + 255) / 256, 256>>>(edge_index, edge_weight);

    dim3 mblk(NDIM, NODES_PER_BLK);
    k_median <<<(NNODES + NODES_PER_BLK - 1) / NODES_PER_BLK, mblk>>>(x, out);
}

// round 7
// speedup vs baseline: 3.1535x; 1.2821x over previous
#include <cuda_runtime.h>
#include <cuda_bf16.h>
#include <math_constants.h>

// Problem constants (fixed by the dataset)
#define NNODES 50000
#define NDIM   64
#define NEDGES 800000

// -------- device scratch (no allocation allowed) --------
__device__ int   g_deg[NNODES];
__device__ int   g_cursor[NNODES];
__device__ int   g_starts[NNODES];
__device__ int   g_total;
__device__ int2  g_edge[NEDGES];    // (src_row, bitcast(weight)) packed

// -------- kernel 1: zero counters --------
__global__ void k_zero() {
    int i = blockIdx.x * blockDim.x + threadIdx.x;
    if (i < NNODES) {
        g_deg[i] = 0;
        g_cursor[i] = 0;
    }
    if (i == 0) g_total = 0;
}

// -------- kernel 2: count in-degree --------
__global__ void k_count(const int* __restrict__ edge_index) {
    int e = blockIdx.x * blockDim.x + threadIdx.x;
    if (e < NEDGES) {
        int dst = edge_index[NEDGES + e];   // edge_index[1, e]
        atomicAdd(&g_deg[dst], 1);
    }
}

// -------- kernel 3: segment offsets (block scan + global atomic base) --------
// Segment ordering across blocks is nondeterministic, but segments are
// disjoint and the median is order-invariant -> output deterministic.
#define OFF_BS 256
__global__ void k_offsets() {
    __shared__ int sh[OFF_BS];
    __shared__ int base;
    int tid = threadIdx.x;
    int gid = blockIdx.x * OFF_BS + tid;
    int v = (gid < NNODES) ? g_deg[gid] : 0;
    sh[tid] = v;
    __syncthreads();
    for (int off = 1; off < OFF_BS; off <<= 1) {
        int t = (tid >= off) ? sh[tid - off] : 0;
        __syncthreads();
        sh[tid] += t;
        __syncthreads();
    }
    if (tid == OFF_BS - 1) base = atomicAdd(&g_total, sh[tid]);
    __syncthreads();
    if (gid < NNODES) g_starts[gid] = base + sh[tid] - v;
}

// -------- kernel 4: scatter (counting sort by destination) --------
__global__ void k_scatter(const int* __restrict__ edge_index,
                          const float* __restrict__ edge_weight) {
    int e = blockIdx.x * blockDim.x + threadIdx.x;
    if (e >= NEDGES) return;
    int src = edge_index[e];
    int dst = edge_index[NEDGES + e];
    float w = edge_weight[e];
    int p = atomicAdd(&g_cursor[dst], 1);
    g_edge[g_starts[dst] + p] = make_int2(src, __float_as_int(w));
}

// -------- pruned Batcher odd-even merge network --------
// Ascending comparators only (lo -> lower wire). With +inf on wires >= deg,
// those wires hold +inf forever, so every comparator with high wire >= D can
// be removed at compile time -> valid D-element network, v[] needs D regs.
__device__ __forceinline__ void cas_f(float& a, float& b) {
    float lo = fminf(a, b);
    float hi = fmaxf(a, b);
    a = lo; b = hi;
}

template<int D, int LO, int N, int R>
struct OEMergeD {
    static __device__ __forceinline__ void run(float* v) {
        constexpr int M = R * 2;
        if constexpr (LO >= D) return;
        else if constexpr (M < N) {
            OEMergeD<D, LO, N, M>::run(v);
            OEMergeD<D, LO + R, N, M>::run(v);
#pragma unroll
            for (int i = LO + R; i + R < LO + N; i += M)
                if (i + R < D) cas_f(v[i], v[i + R]);   // folds at compile time
        } else {
            if constexpr (LO + R < D) cas_f(v[LO], v[LO + R]);
        }
    }
};

template<int D, int LO, int N>
struct OESortD {
    static __device__ __forceinline__ void run(float* v) {
        if constexpr (LO >= D || N <= 1) return;
        else {
            constexpr int M = N / 2;
            OESortD<D, LO, M>::run(v);
            OESortD<D, LO + M, M>::run(v);
            OEMergeD<D, LO, N, 1>::run(v);
        }
    }
};

// -------- register gather + pruned sort + k-select for degree bucket D --------
template<int D>
__device__ __forceinline__ float median_reg(const int2* __restrict__ stage,
                                            const float* __restrict__ x,
                                            int d, int deg, int k) {
    constexpr int P = (D <= 8) ? 8 : (D <= 16) ? 16 : 32;   // parent pow2 network
    float v[D];
#pragma unroll
    for (int j = 0; j < D; j++) {
        if (j < deg) {
            int2 e = stage[j];
            v[j] = x[e.x * NDIM + d] * __int_as_float(e.y);
        } else {
            v[j] = CUDART_INF_F;
        }
    }
    OESortD<D, 0, P>::run(v);
    float r = v[0];
#pragma unroll
    for (int i = 1; i < D; i++) r = (k == i) ? v[i] : r;
    return r;
}

// -------- kernel 5: per-node per-channel lower median --------
// 4 nodes/block, 2 warps/node. Warps are fully independent: each warp stages
// its node's edge list into its own smem slice (__syncwarp only, no block
// barriers), so degree buckets can differ freely across warps.
#define NODES_PER_BLK 4
__global__ void __launch_bounds__(NDIM * NODES_PER_BLK)
k_median(const float* __restrict__ x, float* __restrict__ out) {
    __shared__ int2 stage_s[NODES_PER_BLK * 2][32];

    int n = blockIdx.x * NODES_PER_BLK + threadIdx.y;
    int d = threadIdx.x;
    if (n >= NNODES) return;

    int deg = g_deg[n];
    if (deg == 0) {
        out[n * NDIM + d] = 0.0f;
        return;
    }
    int s = g_starts[n];
    int k = (deg - 1) >> 1;

    if (deg <= 32) {
        int wi   = threadIdx.y * 2 + (d >> 5);
        int lane = d & 31;
        if (lane < deg) stage_s[wi][lane] = g_edge[s + lane];
        __syncwarp();
        const int2* st = stage_s[wi];

        float med;
        if      (deg <= 8)  med = median_reg<8> (st, x, d, deg, k);
        else if (deg <= 12) med = median_reg<12>(st, x, d, deg, k);
        else if (deg <= 16) med = median_reg<16>(st, x, d, deg, k);
        else if (deg <= 20) med = median_reg<20>(st, x, d, deg, k);
        else if (deg <= 24) med = median_reg<24>(st, x, d, deg, k);
        else if (deg <= 28) med = median_reg<28>(st, x, d, deg, k);
        else                med = median_reg<32>(st, x, d, deg, k);
        out[n * NDIM + d] = med;
    } else {
        // Rare path (P(deg>32) ~ 1e-4 per node): global rank-count selection.
        float med = 0.0f;
        for (int i = 0; i < deg; i++) {
            int2 ei = g_edge[s + i];
            float vi = x[ei.x * NDIM + d] * __int_as_float(ei.y);
            int less = 0, eq = 0;
            for (int j = 0; j < deg; j++) {
                int2 ej = g_edge[s + j];
                float vj = x[ej.x * NDIM + d] * __int_as_float(ej.y);
                less += (vj < vi);
                eq   += (vj == vi);
            }
            if (less <= k && k < less + eq) { med = vi; break; }
        }
        out[n * NDIM + d] = med;
    }
}

extern "C" void kernel_launch(void* const* d_in, const int* in_sizes, int n_in,
                              void* d_out, int out_size) {
    const float* x           = (const float*)d_in[0];
    const int*   edge_index  = (const int*)d_in[1];
    const float* edge_weight = (const float*)d_in[2];
    float*       out         = (float*)d_out;

    (void)in_sizes; (void)n_in; (void)out_size;

    k_zero   <<<(NNODES + 255) / 256, 256>>>();
    k_count  <<<(NEDGES + 255) / 256, 256>>>(edge_index);
    k_offsets<<<(NNODES + OFF_BS - 1) / OFF_BS, OFF_BS>>>();
    k_scatter<<<(NEDGES + 255) / 256, 256>>>(edge_index, edge_weight);

    dim3 mblk(NDIM, NODES_PER_BLK);
    k_median <<<(NNODES + NODES_PER_BLK - 1) / NODES_PER_BLK, mblk>>>(x, out);
}